// round 16
// baseline (speedup 1.0000x reference)
#include <cuda_runtime.h>
#include <cuda_fp16.h>
#include <math.h>

// ---------------- problem constants ----------------
#define BS 8
#define NQ 900
#define DM 256
#define NH 8
#define NL 3
#define NP 4
#define DH 32
#define SUMHW 21504           // 128*128 + 64*64 + 32*32
#define NOFF 192              // NH*NL*NP*2
#define NATT 96               // NH*NL*NP
#define QS  (NOFF + NATT)     // 288

// ---------------- scratch ----------------
__device__ float  g_value[(size_t)BS * SUMHW * DM];   // 176 MB
__device__ float  g_qproj[(size_t)BS * NQ * QS];      // 8.3 MB
__device__ float  g_acc[(size_t)BS * NQ * DM];
__device__ float  g_bcat[QS];
__device__ __half g_wvalT_h[DM * DM];                 // W_val^T fp16 [n][k]
__device__ __half g_wcatT_h[QS * DM];                 // (W_off|W_attn)^T fp16 [n][k]
__device__ __half g_woutT_h[DM * DM];                 // W_out^T fp16 [n][k]

// ---------------- ptx helpers ----------------
__device__ __forceinline__ void cp16(unsigned dst, const void* src) {
    asm volatile("cp.async.cg.shared.global [%0], [%1], 16;\n" :: "r"(dst), "l"(src));
}
__device__ __forceinline__ void mma_f16(float c[4], const unsigned a[4],
                                        unsigned b0, unsigned b1) {
    asm volatile(
        "mma.sync.aligned.m16n8k16.row.col.f32.f16.f16.f32 "
        "{%0,%1,%2,%3}, {%4,%5,%6,%7}, {%8,%9}, {%0,%1,%2,%3};\n"
        : "+f"(c[0]), "+f"(c[1]), "+f"(c[2]), "+f"(c[3])
        : "r"(a[0]), "r"(a[1]), "r"(a[2]), "r"(a[3]), "r"(b0), "r"(b1));
}
__device__ __forceinline__ void ldsm4(unsigned& r0, unsigned& r1, unsigned& r2,
                                      unsigned& r3, unsigned addr) {
    asm volatile("ldmatrix.sync.aligned.m8n8.x4.shared.b16 {%0,%1,%2,%3}, [%4];"
                 : "=r"(r0), "=r"(r1), "=r"(r2), "=r"(r3) : "r"(addr));
}
// pack 8 floats -> 8 fp16 in a uint4
__device__ __forceinline__ uint4 pack8h(const float* f) {
    uint4 r;
    __half2 h;
    h = __floats2half2_rn(f[0], f[1]); r.x = *reinterpret_cast<unsigned*>(&h);
    h = __floats2half2_rn(f[2], f[3]); r.y = *reinterpret_cast<unsigned*>(&h);
    h = __floats2half2_rn(f[4], f[5]); r.z = *reinterpret_cast<unsigned*>(&h);
    h = __floats2half2_rn(f[6], f[7]); r.w = *reinterpret_cast<unsigned*>(&h);
    return r;
}

// ============ unified fp16 GEMM: two independent GEMM jobs in one grid =====
// Job0: C0[M0,N0] = A0 @ Bt0^T + bias0   (blocks [0, nb0))
// Job1: C1[M1,N1] = A1 @ Bt1^T + bias1   (blocks [nb0, nb0+nb1))
// K=256.  BM=128, BN=128, 256 thr, 8 warps, warp tile 32x64, ldmatrix.
// Smem rows of 64B (32 halves), 16B-chunk swizzle c ^= (row>>1)&3.
__global__ __launch_bounds__(256, 2) void gemm_f16_uni(
    const float* __restrict__ A0, const __half* __restrict__ Bt0,
    const float* __restrict__ bias0, float* __restrict__ C0,
    int M0, int N0, int nbx0, int nb0,
    const float* __restrict__ A1, const __half* __restrict__ Bt1,
    const float* __restrict__ bias1, float* __restrict__ C1,
    int M1, int N1, int nbx1)
{
    extern __shared__ char smem[];
    char* Asm = smem;                       // [2][8192]
    char* Bsm = smem + 16384;               // [2][8192]
    const unsigned sA = (unsigned)__cvta_generic_to_shared(Asm);
    const unsigned sB = (unsigned)__cvta_generic_to_shared(Bsm);

    // ---- job select (block-uniform) ----
    const float* A; const __half* Bt; const float* bias; float* C;
    int M, N, bm, bn;
    {
        const int bid = blockIdx.x;
        if (bid < nb0) {
            A = A0; Bt = Bt0; bias = bias0; C = C0; M = M0; N = N0;
            bn = (bid % nbx0) * 128; bm = (bid / nbx0) * 128;
        } else {
            const int q = bid - nb0;
            A = A1; Bt = Bt1; bias = bias1; C = C1; M = M1; N = N1;
            bn = (q % nbx1) * 128; bm = (q / nbx1) * 128;
        }
    }

    const int tid = threadIdx.x;
    const int wid = tid >> 5, lane = tid & 31;
    const int g = lane >> 2, t4 = lane & 3;
    const int warp_m = (wid >> 1) * 32;     // 0,32,64,96
    const int warp_n = (wid & 1) * 64;      // 0,64

    const int a_row0 = warp_m + (lane & 7) + ((lane >> 3) & 1) * 8;
    const int a_csel = lane >> 4;
    const int a_rsw  = (a_row0 >> 1) & 3;
    const int b_sel  = lane >> 3;
    const int b_row0 = warp_n + (b_sel >> 1) * 8 + (lane & 7);
    const int b_cadd = b_sel & 1;
    const int b_rsw  = (b_row0 >> 1) & 3;

    const int lm = tid >> 1;
    const int cb = (tid & 1) * 2;
    const int lk = (tid & 1) * 16;

    const int arow = min(bm + lm, M - 1);
    const int brow = min(bn + lm, N - 1);

    float4 ra[4];

    auto ldgA = [&](int t) {
        const float* Ag = A + (size_t)arow * 256 + t * 32 + lk;
#pragma unroll
        for (int p = 0; p < 4; p++)
            ra[p] = *reinterpret_cast<const float4*>(Ag + p * 4);
    };
    auto stsA = [&](int s) {
        const int sw = (lm >> 1) & 3;
        char* base = Asm + s * 8192 + lm * 64;
        *reinterpret_cast<uint4*>(base + (((cb)     ^ sw) << 4)) = pack8h(&ra[0].x);
        *reinterpret_cast<uint4*>(base + (((cb + 1) ^ sw) << 4)) = pack8h(&ra[2].x);
    };
    auto cpB = [&](int t, int s) {
        const __half* Bg = Bt + (size_t)brow * 256 + t * 32 + cb * 8;
        const int sw = (lm >> 1) & 3;
        unsigned base = sB + s * 8192 + lm * 64;
        cp16(base + (((cb)     ^ sw) << 4), Bg);
        cp16(base + (((cb + 1) ^ sw) << 4), Bg + 8);
        asm volatile("cp.async.commit_group;\n");
    };

    float c[2][8][4];
#pragma unroll
    for (int mi = 0; mi < 2; mi++)
#pragma unroll
        for (int nj = 0; nj < 8; nj++)
#pragma unroll
            for (int r = 0; r < 4; r++) c[mi][nj][r] = 0.f;

    cpB(0, 0);
    ldgA(0);
    stsA(0);

#pragma unroll 1
    for (int t = 0; t < 8; t++) {
        if (t + 1 < 8) {
            ldgA(t + 1);
            cpB(t + 1, (t + 1) & 1);
            asm volatile("cp.async.wait_group 1;\n" ::: "memory");
        } else {
            asm volatile("cp.async.wait_group 0;\n" ::: "memory");
        }
        __syncthreads();

        const unsigned aB = sA + (t & 1) * 8192;
        const unsigned bB = sB + (t & 1) * 8192;

#pragma unroll
        for (int kk = 0; kk < 2; kk++) {
            const int c0 = 2 * kk;
            unsigned a[2][4];
#pragma unroll
            for (int mi = 0; mi < 2; mi++) {
                const int row = a_row0 + mi * 16;
                ldsm4(a[mi][0], a[mi][1], a[mi][2], a[mi][3],
                      aB + row * 64 + (((c0 + a_csel) ^ a_rsw) << 4));
            }
            unsigned b[4][4];
#pragma unroll
            for (int j = 0; j < 4; j++) {
                const int nrow = b_row0 + j * 16;
                ldsm4(b[j][0], b[j][1], b[j][2], b[j][3],
                      bB + nrow * 64 + (((c0 + b_cadd) ^ b_rsw) << 4));
            }
#pragma unroll
            for (int j = 0; j < 4; j++) {
                mma_f16(c[0][2 * j],     a[0], b[j][0], b[j][1]);
                mma_f16(c[1][2 * j],     a[1], b[j][0], b[j][1]);
                mma_f16(c[0][2 * j + 1], a[0], b[j][2], b[j][3]);
                mma_f16(c[1][2 * j + 1], a[1], b[j][2], b[j][3]);
            }
        }

        if (t + 1 < 8) {
            __syncthreads();
            stsA((t + 1) & 1);
        }
    }

#pragma unroll
    for (int mi = 0; mi < 2; mi++) {
        const int r0 = bm + warp_m + mi * 16 + g;
#pragma unroll
        for (int nj = 0; nj < 8; nj++) {
            const int col = bn + warp_n + nj * 8 + 2 * t4;
            if (col < N) {
                const float bx = bias[col], by = bias[col + 1];
                if (r0 < M) {
                    float2 v0 = make_float2(c[mi][nj][0] + bx, c[mi][nj][1] + by);
                    *reinterpret_cast<float2*>(C + (size_t)r0 * N + col) = v0;
                }
                if (r0 + 8 < M) {
                    float2 v1 = make_float2(c[mi][nj][2] + bx, c[mi][nj][3] + by);
                    *reinterpret_cast<float2*>(C + (size_t)(r0 + 8) * N + col) = v1;
                }
            }
        }
    }
}

// ---------------- weight prep (tiny) ---------------------------------------
__global__ void transpose_half_n(const float* __restrict__ W, __half* __restrict__ Wt,
                                 int ncols)
{
    int i = blockIdx.x * blockDim.x + threadIdx.x;   // i = n*256 + k
    if (i < ncols * DM) {
        int n = i >> 8, k = i & 255;
        Wt[i] = __float2half(W[k * ncols + n]);
    }
}
__global__ void concat_w_t(const float* __restrict__ W_off, const float* __restrict__ b_off,
                           const float* __restrict__ W_attn, const float* __restrict__ b_attn,
                           __half* __restrict__ WcatT, float* __restrict__ bcat)
{
    int i = blockIdx.x * blockDim.x + threadIdx.x;   // i = n*256 + k
    if (i < QS * DM) {
        int n = i >> 8, k = i & 255;
        float v = (n < NOFF) ? W_off[k * NOFF + n] : W_attn[k * NATT + (n - NOFF)];
        WcatT[i] = __float2half(v);
    }
    if (i < QS)
        bcat[i] = (i < NOFF) ? b_off[i] : b_attn[i - NOFF];
}

// ---------------- sampling v2: lane-parallel point precompute --------------
__global__ __launch_bounds__(256) void msda_sample2(
    const float* __restrict__ refp_g,   // [BS, NQ, NL, 2]
    const float* __restrict__ qproj_g,  // [BS, NQ, QS]  (off | att)
    const float* __restrict__ value_g,  // [BS, SUMHW, DM]
    float* __restrict__ acc_g)          // [BS, NQ, DM]
{
    __shared__ float sdata[8][96];

    const int wlocal = threadIdx.x >> 5;
    const int gwarp  = (blockIdx.x * blockDim.x + threadIdx.x) >> 5;
    const int lane   = threadIdx.x & 31;
    if (gwarp >= BS * NQ * NH) return;

    const int h  = gwarp & (NH - 1);
    const int bq = gwarp >> 3;
    const int b  = bq / NQ;

    float* sp = sdata[wlocal];

    {
        const int i = lane;
        float v = -INFINITY;
        if (i < 12) v = qproj_g[(size_t)bq * QS + NOFF + h * 12 + i];
        float mx = v;
#pragma unroll
        for (int o = 8; o; o >>= 1) mx = fmaxf(mx, __shfl_xor_sync(0xffffffffu, mx, o, 16));
        float e = (i < 12) ? expf(v - mx) : 0.f;
        float s = e;
#pragma unroll
        for (int o = 8; o; o >>= 1) s += __shfl_xor_sync(0xffffffffu, s, o, 16);

        if (i < 12) {
            const float aw = e / s;
            const int l   = i >> 2;
            const int Dim = 128 >> l;                    // 128,64,32
            const int st  = (l == 0) ? 0 : (l == 1) ? 16384 : 20480;
            const float ref_x = refp_g[(size_t)bq * (NL * 2) + 2 * l];
            const float ref_y = refp_g[(size_t)bq * (NL * 2) + 2 * l + 1];
            const float ox = qproj_g[(size_t)bq * QS + h * 24 + 2 * i];
            const float oy = qproj_g[(size_t)bq * QS + h * 24 + 2 * i + 1];

            const float px = ref_x * (float)Dim + ox - 0.5f;
            const float py = ref_y * (float)Dim + oy - 0.5f;
            const float fx = floorf(px), fy = floorf(py);
            const float lx = px - fx, ly = py - fy;
            const int x0 = (int)fx, y0 = (int)fy;

            const bool vx0 = ((unsigned)x0       < (unsigned)Dim);
            const bool vx1 = ((unsigned)(x0 + 1) < (unsigned)Dim);
            const bool vy0 = ((unsigned)y0       < (unsigned)Dim);
            const bool vy1 = ((unsigned)(y0 + 1) < (unsigned)Dim);

            const int cx0 = min(max(x0, 0), Dim - 1);
            const int cx1 = min(max(x0 + 1, 0), Dim - 1);
            const int cy0 = min(max(y0, 0), Dim - 1);
            const int cy1 = min(max(y0 + 1, 0), Dim - 1);

            sp[i * 8 + 0] = (vx0 && vy0) ? aw * (1.f - lx) * (1.f - ly) : 0.f;
            sp[i * 8 + 1] = (vx1 && vy0) ? aw * lx * (1.f - ly) : 0.f;
            sp[i * 8 + 2] = (vx0 && vy1) ? aw * (1.f - lx) * ly : 0.f;
            sp[i * 8 + 3] = (vx1 && vy1) ? aw * lx * ly : 0.f;
            sp[i * 8 + 4] = __int_as_float((st + cy0 * Dim + cx0) * DM);
            sp[i * 8 + 5] = __int_as_float((st + cy0 * Dim + cx1) * DM);
            sp[i * 8 + 6] = __int_as_float((st + cy1 * Dim + cx0) * DM);
            sp[i * 8 + 7] = __int_as_float((st + cy1 * Dim + cx1) * DM);
        }
    }
    __syncwarp();

    const float* vb = value_g + (size_t)b * SUMHW * DM + h * DH + lane;
    float a0 = 0.f, a1 = 0.f;
#pragma unroll
    for (int i = 0; i < 12; i++) {
        const float m00 = sp[i * 8 + 0];
        const float m10 = sp[i * 8 + 1];
        const float m01 = sp[i * 8 + 2];
        const float m11 = sp[i * 8 + 3];
        const int i00 = __float_as_int(sp[i * 8 + 4]);
        const int i10 = __float_as_int(sp[i * 8 + 5]);
        const int i01 = __float_as_int(sp[i * 8 + 6]);
        const int i11 = __float_as_int(sp[i * 8 + 7]);
        a0 = fmaf(m00, vb[i00], a0);
        a1 = fmaf(m10, vb[i10], a1);
        a0 = fmaf(m01, vb[i01], a0);
        a1 = fmaf(m11, vb[i11], a1);
    }
    acc_g[(size_t)bq * DM + h * DH + lane] = a0 + a1;
}

// ---------------- launch ---------------------------------------------------
extern "C" void kernel_launch(void* const* d_in, const int* in_sizes, int n_in,
                              void* d_out, int out_size)
{
    const float* query  = (const float*)d_in[0];
    const float* refpts = (const float*)d_in[1];
    const float* inflat = (const float*)d_in[2];
    const float* W_off  = (const float*)d_in[5];
    const float* b_off  = (const float*)d_in[6];
    const float* W_attn = (const float*)d_in[7];
    const float* b_attn = (const float*)d_in[8];
    const float* W_val  = (const float*)d_in[9];
    const float* b_val  = (const float*)d_in[10];
    const float* W_out  = (const float*)d_in[11];
    const float* b_out  = (const float*)d_in[12];
    float* out = (float*)d_out;

    float *value, *qproj, *acc, *bcat;
    __half *wvalT, *wcatT, *woutT;
    cudaGetSymbolAddress((void**)&value, g_value);
    cudaGetSymbolAddress((void**)&qproj, g_qproj);
    cudaGetSymbolAddress((void**)&acc,   g_acc);
    cudaGetSymbolAddress((void**)&bcat,  g_bcat);
    cudaGetSymbolAddress((void**)&wvalT, g_wvalT_h);
    cudaGetSymbolAddress((void**)&wcatT, g_wcatT_h);
    cudaGetSymbolAddress((void**)&woutT, g_woutT_h);

    const int MQ = BS * NQ;          // 7200
    const int MV = BS * SUMHW;       // 172032
    const int smem_v = 32768;        // 32 KB

    cudaFuncSetAttribute(gemm_f16_uni, cudaFuncAttributeMaxDynamicSharedMemorySize, smem_v);

    // 0) weight prep (tiny)
    concat_w_t<<<(QS * DM + 255) / 256, 256>>>(W_off, b_off, W_attn, b_attn, wcatT, bcat);
    transpose_half_n<<<(DM * DM + 255) / 256, 256>>>(W_val, wvalT, DM);
    transpose_half_n<<<(DM * DM + 255) / 256, 256>>>(W_out, woutT, DM);

    // 1+2) fused: value projection (job0) + q projection (job1) in one grid
    {
        const int nb0  = 2 * (MV / 128);                 // 2688 value blocks
        const int nbx1 = 3;                              // ceil(288/128)
        const int nb1  = nbx1 * ((MQ + 127) / 128);      // 171 q-proj blocks
        gemm_f16_uni<<<nb0 + nb1, 256, smem_v>>>(
            inflat, wvalT, b_val, value, MV, DM, 2, nb0,
            query,  wcatT, bcat,  qproj, MQ, QS, nbx1);
    }

    // 3) sampling (lane-parallel precompute)
    {
        const int warps = BS * NQ * NH;
        const int blocks = (warps * 32 + 255) / 256;
        msda_sample2<<<blocks, 256>>>(refpts, qproj, value, acc);
    }

    // 4) output projection: [7200,256] @ [256,256] -> d_out  (job0 only)
    {
        const int nb0 = 2 * ((MQ + 127) / 128);          // 114 blocks
        gemm_f16_uni<<<nb0, 256, smem_v>>>(
            acc, woutT, b_out, out, MQ, DM, 2, nb0,
            acc, woutT, b_out, out, MQ, DM, 2);
    }
}

// round 17
// speedup vs baseline: 1.0268x; 1.0268x over previous
#include <cuda_runtime.h>
#include <cuda_fp16.h>
#include <math.h>

// ---------------- problem constants ----------------
#define BS 8
#define NQ 900
#define DM 256
#define NH 8
#define NL 3
#define NP 4
#define DH 32
#define SUMHW 21504           // 128*128 + 64*64 + 32*32
#define NOFF 192              // NH*NL*NP*2
#define NATT 96               // NH*NL*NP
#define QS  (NOFF + NATT)     // 288

// ---------------- scratch ----------------
__device__ __half g_value_h[(size_t)BS * SUMHW * DM]; // 88 MB (fp16 value)
__device__ float  g_qproj[(size_t)BS * NQ * QS];      // 8.3 MB
__device__ float  g_acc[(size_t)BS * NQ * DM];
__device__ float  g_bcat[QS];
__device__ __half g_wvalT_h[DM * DM];                 // W_val^T fp16 [n][k]
__device__ __half g_wcatT_h[QS * DM];                 // (W_off|W_attn)^T fp16 [n][k]
__device__ __half g_woutT_h[DM * DM];                 // W_out^T fp16 [n][k]

// ---------------- ptx helpers ----------------
__device__ __forceinline__ void cp16(unsigned dst, const void* src) {
    asm volatile("cp.async.cg.shared.global [%0], [%1], 16;\n" :: "r"(dst), "l"(src));
}
__device__ __forceinline__ void mma_f16(float c[4], const unsigned a[4],
                                        unsigned b0, unsigned b1) {
    asm volatile(
        "mma.sync.aligned.m16n8k16.row.col.f32.f16.f16.f32 "
        "{%0,%1,%2,%3}, {%4,%5,%6,%7}, {%8,%9}, {%0,%1,%2,%3};\n"
        : "+f"(c[0]), "+f"(c[1]), "+f"(c[2]), "+f"(c[3])
        : "r"(a[0]), "r"(a[1]), "r"(a[2]), "r"(a[3]), "r"(b0), "r"(b1));
}
__device__ __forceinline__ void ldsm4(unsigned& r0, unsigned& r1, unsigned& r2,
                                      unsigned& r3, unsigned addr) {
    asm volatile("ldmatrix.sync.aligned.m8n8.x4.shared.b16 {%0,%1,%2,%3}, [%4];"
                 : "=r"(r0), "=r"(r1), "=r"(r2), "=r"(r3) : "r"(addr));
}
// pack 8 floats -> 8 fp16 in a uint4
__device__ __forceinline__ uint4 pack8h(const float* f) {
    uint4 r;
    __half2 h;
    h = __floats2half2_rn(f[0], f[1]); r.x = *reinterpret_cast<unsigned*>(&h);
    h = __floats2half2_rn(f[2], f[3]); r.y = *reinterpret_cast<unsigned*>(&h);
    h = __floats2half2_rn(f[4], f[5]); r.z = *reinterpret_cast<unsigned*>(&h);
    h = __floats2half2_rn(f[6], f[7]); r.w = *reinterpret_cast<unsigned*>(&h);
    return r;
}

// ============ unified fp16 GEMM: two independent GEMM jobs in one grid =====
// Job i: Ci[Mi,Ni] = Ai @ Bti^T + biasi.  houti: 1 -> fp16 output, 0 -> fp32.
// K=256.  BM=128, BN=128, 256 thr, 8 warps, warp tile 32x64, ldmatrix.
__global__ __launch_bounds__(256, 2) void gemm_f16_uni(
    const float* __restrict__ A0, const __half* __restrict__ Bt0,
    const float* __restrict__ bias0, void* __restrict__ C0,
    int M0, int N0, int nbx0, int nb0, int hout0,
    const float* __restrict__ A1, const __half* __restrict__ Bt1,
    const float* __restrict__ bias1, void* __restrict__ C1,
    int M1, int N1, int nbx1, int hout1)
{
    extern __shared__ char smem[];
    char* Asm = smem;                       // [2][8192]
    char* Bsm = smem + 16384;               // [2][8192]
    const unsigned sA = (unsigned)__cvta_generic_to_shared(Asm);
    const unsigned sB = (unsigned)__cvta_generic_to_shared(Bsm);

    // ---- job select (block-uniform) ----
    const float* A; const __half* Bt; const float* bias; void* C;
    int M, N, bm, bn, hout;
    {
        const int bid = blockIdx.x;
        if (bid < nb0) {
            A = A0; Bt = Bt0; bias = bias0; C = C0; M = M0; N = N0; hout = hout0;
            bn = (bid % nbx0) * 128; bm = (bid / nbx0) * 128;
        } else {
            const int q = bid - nb0;
            A = A1; Bt = Bt1; bias = bias1; C = C1; M = M1; N = N1; hout = hout1;
            bn = (q % nbx1) * 128; bm = (q / nbx1) * 128;
        }
    }

    const int tid = threadIdx.x;
    const int wid = tid >> 5, lane = tid & 31;
    const int g = lane >> 2, t4 = lane & 3;
    const int warp_m = (wid >> 1) * 32;     // 0,32,64,96
    const int warp_n = (wid & 1) * 64;      // 0,64

    const int a_row0 = warp_m + (lane & 7) + ((lane >> 3) & 1) * 8;
    const int a_csel = lane >> 4;
    const int a_rsw  = (a_row0 >> 1) & 3;
    const int b_sel  = lane >> 3;
    const int b_row0 = warp_n + (b_sel >> 1) * 8 + (lane & 7);
    const int b_cadd = b_sel & 1;
    const int b_rsw  = (b_row0 >> 1) & 3;

    const int lm = tid >> 1;
    const int cb = (tid & 1) * 2;
    const int lk = (tid & 1) * 16;

    const int arow = min(bm + lm, M - 1);
    const int brow = min(bn + lm, N - 1);

    float4 ra[4];

    auto ldgA = [&](int t) {
        const float* Ag = A + (size_t)arow * 256 + t * 32 + lk;
#pragma unroll
        for (int p = 0; p < 4; p++)
            ra[p] = *reinterpret_cast<const float4*>(Ag + p * 4);
    };
    auto stsA = [&](int s) {
        const int sw = (lm >> 1) & 3;
        char* base = Asm + s * 8192 + lm * 64;
        *reinterpret_cast<uint4*>(base + (((cb)     ^ sw) << 4)) = pack8h(&ra[0].x);
        *reinterpret_cast<uint4*>(base + (((cb + 1) ^ sw) << 4)) = pack8h(&ra[2].x);
    };
    auto cpB = [&](int t, int s) {
        const __half* Bg = Bt + (size_t)brow * 256 + t * 32 + cb * 8;
        const int sw = (lm >> 1) & 3;
        unsigned base = sB + s * 8192 + lm * 64;
        cp16(base + (((cb)     ^ sw) << 4), Bg);
        cp16(base + (((cb + 1) ^ sw) << 4), Bg + 8);
        asm volatile("cp.async.commit_group;\n");
    };

    float c[2][8][4];
#pragma unroll
    for (int mi = 0; mi < 2; mi++)
#pragma unroll
        for (int nj = 0; nj < 8; nj++)
#pragma unroll
            for (int r = 0; r < 4; r++) c[mi][nj][r] = 0.f;

    cpB(0, 0);
    ldgA(0);
    stsA(0);

#pragma unroll 1
    for (int t = 0; t < 8; t++) {
        if (t + 1 < 8) {
            ldgA(t + 1);
            cpB(t + 1, (t + 1) & 1);
            asm volatile("cp.async.wait_group 1;\n" ::: "memory");
        } else {
            asm volatile("cp.async.wait_group 0;\n" ::: "memory");
        }
        __syncthreads();

        const unsigned aB = sA + (t & 1) * 8192;
        const unsigned bB = sB + (t & 1) * 8192;

#pragma unroll
        for (int kk = 0; kk < 2; kk++) {
            const int c0 = 2 * kk;
            unsigned a[2][4];
#pragma unroll
            for (int mi = 0; mi < 2; mi++) {
                const int row = a_row0 + mi * 16;
                ldsm4(a[mi][0], a[mi][1], a[mi][2], a[mi][3],
                      aB + row * 64 + (((c0 + a_csel) ^ a_rsw) << 4));
            }
            unsigned b[4][4];
#pragma unroll
            for (int j = 0; j < 4; j++) {
                const int nrow = b_row0 + j * 16;
                ldsm4(b[j][0], b[j][1], b[j][2], b[j][3],
                      bB + nrow * 64 + (((c0 + b_cadd) ^ b_rsw) << 4));
            }
#pragma unroll
            for (int j = 0; j < 4; j++) {
                mma_f16(c[0][2 * j],     a[0], b[j][0], b[j][1]);
                mma_f16(c[1][2 * j],     a[1], b[j][0], b[j][1]);
                mma_f16(c[0][2 * j + 1], a[0], b[j][2], b[j][3]);
                mma_f16(c[1][2 * j + 1], a[1], b[j][2], b[j][3]);
            }
        }

        if (t + 1 < 8) {
            __syncthreads();
            stsA((t + 1) & 1);
        }
    }

    // ---- epilogue: bias + store (fp16 or fp32 per job) ----
#pragma unroll
    for (int mi = 0; mi < 2; mi++) {
        const int r0 = bm + warp_m + mi * 16 + g;
#pragma unroll
        for (int nj = 0; nj < 8; nj++) {
            const int col = bn + warp_n + nj * 8 + 2 * t4;
            if (col < N) {
                const float bx = bias[col], by = bias[col + 1];
                const float x0 = c[mi][nj][0] + bx, y0v = c[mi][nj][1] + by;
                const float x1 = c[mi][nj][2] + bx, y1v = c[mi][nj][3] + by;
                if (hout) {
                    __half* Ch = (__half*)C;
                    if (r0 < M)
                        *reinterpret_cast<__half2*>(Ch + (size_t)r0 * N + col) =
                            __floats2half2_rn(x0, y0v);
                    if (r0 + 8 < M)
                        *reinterpret_cast<__half2*>(Ch + (size_t)(r0 + 8) * N + col) =
                            __floats2half2_rn(x1, y1v);
                } else {
                    float* Cf = (float*)C;
                    if (r0 < M)
                        *reinterpret_cast<float2*>(Cf + (size_t)r0 * N + col) =
                            make_float2(x0, y0v);
                    if (r0 + 8 < M)
                        *reinterpret_cast<float2*>(Cf + (size_t)(r0 + 8) * N + col) =
                            make_float2(x1, y1v);
                }
            }
        }
    }
}

// ---------------- weight prep (tiny) ---------------------------------------
__global__ void transpose_half_n(const float* __restrict__ W, __half* __restrict__ Wt,
                                 int ncols)
{
    int i = blockIdx.x * blockDim.x + threadIdx.x;   // i = n*256 + k
    if (i < ncols * DM) {
        int n = i >> 8, k = i & 255;
        Wt[i] = __float2half(W[k * ncols + n]);
    }
}
__global__ void concat_w_t(const float* __restrict__ W_off, const float* __restrict__ b_off,
                           const float* __restrict__ W_attn, const float* __restrict__ b_attn,
                           __half* __restrict__ WcatT, float* __restrict__ bcat)
{
    int i = blockIdx.x * blockDim.x + threadIdx.x;   // i = n*256 + k
    if (i < QS * DM) {
        int n = i >> 8, k = i & 255;
        float v = (n < NOFF) ? W_off[k * NOFF + n] : W_attn[k * NATT + (n - NOFF)];
        WcatT[i] = __float2half(v);
    }
    if (i < QS)
        bcat[i] = (i < NOFF) ? b_off[i] : b_attn[i - NOFF];
}

// ---------------- sampling: lane-parallel precompute, fp16 value -----------
__global__ __launch_bounds__(256) void msda_sample3(
    const float* __restrict__ refp_g,   // [BS, NQ, NL, 2]
    const float* __restrict__ qproj_g,  // [BS, NQ, QS]  (off | att)
    const __half* __restrict__ value_g, // [BS, SUMHW, DM] fp16
    float* __restrict__ acc_g)          // [BS, NQ, DM]
{
    __shared__ float sdata[8][96];

    const int wlocal = threadIdx.x >> 5;
    const int gwarp  = (blockIdx.x * blockDim.x + threadIdx.x) >> 5;
    const int lane   = threadIdx.x & 31;
    if (gwarp >= BS * NQ * NH) return;

    const int h  = gwarp & (NH - 1);
    const int bq = gwarp >> 3;
    const int b  = bq / NQ;

    float* sp = sdata[wlocal];

    {
        const int i = lane;
        float v = -INFINITY;
        if (i < 12) v = qproj_g[(size_t)bq * QS + NOFF + h * 12 + i];
        float mx = v;
#pragma unroll
        for (int o = 8; o; o >>= 1) mx = fmaxf(mx, __shfl_xor_sync(0xffffffffu, mx, o, 16));
        float e = (i < 12) ? expf(v - mx) : 0.f;
        float s = e;
#pragma unroll
        for (int o = 8; o; o >>= 1) s += __shfl_xor_sync(0xffffffffu, s, o, 16);

        if (i < 12) {
            const float aw = e / s;
            const int l   = i >> 2;
            const int Dim = 128 >> l;                    // 128,64,32
            const int st  = (l == 0) ? 0 : (l == 1) ? 16384 : 20480;
            const float ref_x = refp_g[(size_t)bq * (NL * 2) + 2 * l];
            const float ref_y = refp_g[(size_t)bq * (NL * 2) + 2 * l + 1];
            const float ox = qproj_g[(size_t)bq * QS + h * 24 + 2 * i];
            const float oy = qproj_g[(size_t)bq * QS + h * 24 + 2 * i + 1];

            const float px = ref_x * (float)Dim + ox - 0.5f;
            const float py = ref_y * (float)Dim + oy - 0.5f;
            const float fx = floorf(px), fy = floorf(py);
            const float lx = px - fx, ly = py - fy;
            const int x0 = (int)fx, y0 = (int)fy;

            const bool vx0 = ((unsigned)x0       < (unsigned)Dim);
            const bool vx1 = ((unsigned)(x0 + 1) < (unsigned)Dim);
            const bool vy0 = ((unsigned)y0       < (unsigned)Dim);
            const bool vy1 = ((unsigned)(y0 + 1) < (unsigned)Dim);

            const int cx0 = min(max(x0, 0), Dim - 1);
            const int cx1 = min(max(x0 + 1, 0), Dim - 1);
            const int cy0 = min(max(y0, 0), Dim - 1);
            const int cy1 = min(max(y0 + 1, 0), Dim - 1);

            sp[i * 8 + 0] = (vx0 && vy0) ? aw * (1.f - lx) * (1.f - ly) : 0.f;
            sp[i * 8 + 1] = (vx1 && vy0) ? aw * lx * (1.f - ly) : 0.f;
            sp[i * 8 + 2] = (vx0 && vy1) ? aw * (1.f - lx) * ly : 0.f;
            sp[i * 8 + 3] = (vx1 && vy1) ? aw * lx * ly : 0.f;
            sp[i * 8 + 4] = __int_as_float((st + cy0 * Dim + cx0) * DM);
            sp[i * 8 + 5] = __int_as_float((st + cy0 * Dim + cx1) * DM);
            sp[i * 8 + 6] = __int_as_float((st + cy1 * Dim + cx0) * DM);
            sp[i * 8 + 7] = __int_as_float((st + cy1 * Dim + cx1) * DM);
        }
    }
    __syncwarp();

    const __half* vb = value_g + (size_t)b * SUMHW * DM + h * DH + lane;
    float a0 = 0.f, a1 = 0.f;
#pragma unroll
    for (int i = 0; i < 12; i++) {
        const float m00 = sp[i * 8 + 0];
        const float m10 = sp[i * 8 + 1];
        const float m01 = sp[i * 8 + 2];
        const float m11 = sp[i * 8 + 3];
        const int i00 = __float_as_int(sp[i * 8 + 4]);
        const int i10 = __float_as_int(sp[i * 8 + 5]);
        const int i01 = __float_as_int(sp[i * 8 + 6]);
        const int i11 = __float_as_int(sp[i * 8 + 7]);
        a0 = fmaf(m00, __half2float(vb[i00]), a0);
        a1 = fmaf(m10, __half2float(vb[i10]), a1);
        a0 = fmaf(m01, __half2float(vb[i01]), a0);
        a1 = fmaf(m11, __half2float(vb[i11]), a1);
    }
    acc_g[(size_t)bq * DM + h * DH + lane] = a0 + a1;
}

// ---------------- launch ---------------------------------------------------
extern "C" void kernel_launch(void* const* d_in, const int* in_sizes, int n_in,
                              void* d_out, int out_size)
{
    const float* query  = (const float*)d_in[0];
    const float* refpts = (const float*)d_in[1];
    const float* inflat = (const float*)d_in[2];
    const float* W_off  = (const float*)d_in[5];
    const float* b_off  = (const float*)d_in[6];
    const float* W_attn = (const float*)d_in[7];
    const float* b_attn = (const float*)d_in[8];
    const float* W_val  = (const float*)d_in[9];
    const float* b_val  = (const float*)d_in[10];
    const float* W_out  = (const float*)d_in[11];
    const float* b_out  = (const float*)d_in[12];
    float* out = (float*)d_out;

    float *qproj, *acc, *bcat;
    __half *valueh, *wvalT, *wcatT, *woutT;
    cudaGetSymbolAddress((void**)&valueh, g_value_h);
    cudaGetSymbolAddress((void**)&qproj,  g_qproj);
    cudaGetSymbolAddress((void**)&acc,    g_acc);
    cudaGetSymbolAddress((void**)&bcat,   g_bcat);
    cudaGetSymbolAddress((void**)&wvalT,  g_wvalT_h);
    cudaGetSymbolAddress((void**)&wcatT,  g_wcatT_h);
    cudaGetSymbolAddress((void**)&woutT,  g_woutT_h);

    const int MQ = BS * NQ;          // 7200
    const int MV = BS * SUMHW;       // 172032
    const int smem_v = 32768;        // 32 KB

    cudaFuncSetAttribute(gemm_f16_uni, cudaFuncAttributeMaxDynamicSharedMemorySize, smem_v);

    // 0) weight prep (tiny)
    concat_w_t<<<(QS * DM + 255) / 256, 256>>>(W_off, b_off, W_attn, b_attn, wcatT, bcat);
    transpose_half_n<<<(DM * DM + 255) / 256, 256>>>(W_val, wvalT, DM);
    transpose_half_n<<<(DM * DM + 255) / 256, 256>>>(W_out, woutT, DM);

    // 1+2) fused: value projection (job0, fp16 out) + q projection (job1, fp32)
    {
        const int nb0  = 2 * (MV / 128);                 // 2688 value blocks
        const int nbx1 = 3;                              // ceil(288/128)
        const int nb1  = nbx1 * ((MQ + 127) / 128);      // 171 q-proj blocks
        gemm_f16_uni<<<nb0 + nb1, 256, smem_v>>>(
            inflat, wvalT, b_val, valueh, MV, DM, 2, nb0, 1,
            query,  wcatT, bcat,  qproj,  MQ, QS, nbx1, 0);
    }

    // 3) sampling (fp16 value gather)
    {
        const int warps = BS * NQ * NH;
        const int blocks = (warps * 32 + 255) / 256;
        msda_sample3<<<blocks, 256>>>(refpts, qproj, valueh, acc);
    }

    // 4) output projection: [7200,256] @ [256,256] -> d_out (fp32 out)
    {
        const int nb0 = 2 * ((MQ + 127) / 128);          // 114 blocks
        gemm_f16_uni<<<nb0, 256, smem_v>>>(
            acc, woutT, b_out, out, MQ, DM, 2, nb0, 0,
            acc, woutT, b_out, out, MQ, DM, 2, 0);
    }
}